// round 6
// baseline (speedup 1.0000x reference)
#include <cuda_runtime.h>
#include <cuda_bf16.h>
#include <mma.h>
#include <math.h>

// ----------------------------------------------------------------------------
// CapacityRouter via approximate-screen + exact-rescue:
//  wt_kernel:      W[k][64] -> W^T[64][k] scratch
//  screen_kernel:  bf16 wmma GEMM -> approx logits -> top-8 candidates/token
//  rescue_kernel:  exact fp32 sequential-k logits for the 8 candidates ->
//                  top-2 (bit-identical to full exact scan), weights, histogram
//  scan/mask:      ordered capacity masking (unchanged semantics)
// Output: [ idx (N*2) | w (N*2) | mask (N*2) | counters (64) | dropped (1) ]
// ----------------------------------------------------------------------------

#define HD 1024
#define NE 64
#define TOPK 2
#define MAXN (1 << 18)
#define MAXB 8192

#define TOKA 128        // screen: tokens per block
#define TPBA 256
#define CKA 64          // screen k-chunk
#define SA 72           // A_s stride (bf16)
#define SB 72           // B_s stride (bf16)
#define SL 68           // logits stride (f32)

#define TOKR 64         // rescue: tokens per block
#define TPBR 512
#define CKB 128         // rescue k-chunk
#define XBS 132         // rescue smem row stride (floats)
#define NCHB (HD / CKB) // 8

__device__ unsigned char g_cand[(size_t)MAXN * 8];
__device__ float g_WT[NE * HD];
__device__ int g_hist[MAXB * NE];
__device__ int g_base[MAXB * NE];
__device__ int g_edrop[NE];

using namespace nvcuda;

__device__ __forceinline__ void cp_async16(void* smem_dst, const void* gmem_src) {
    unsigned s = (unsigned)__cvta_generic_to_shared(smem_dst);
    asm volatile("cp.async.ca.shared.global [%0], [%1], 16;\n"
                 :: "r"(s), "l"(gmem_src));
}
#define CP_COMMIT() asm volatile("cp.async.commit_group;\n" ::: "memory")
#define CP_WAIT1()  asm volatile("cp.async.wait_group 1;\n" ::: "memory")
#define CP_WAIT0()  asm volatile("cp.async.wait_group 0;\n" ::: "memory")

// ---------------------------------------------------------------------------
// K0: transpose W into g_WT[e][k]
// ---------------------------------------------------------------------------
__global__ void wt_kernel(const float* __restrict__ W) {
    int e = blockIdx.x;
    for (int k = threadIdx.x; k < HD; k += blockDim.x)
        g_WT[e * HD + k] = W[k * NE + e];
}

// sorted-8 insertion (descending value, ascending id on ties)
__device__ __forceinline__ void ins8(float v, int j, float* m, int* id) {
    bool b7 = (v > m[7]) || (v == m[7] && j < id[7]);
    if (b7) {
        m[7] = v; id[7] = j;
#pragma unroll
        for (int s = 7; s > 0; --s) {
            bool b = (m[s] > m[s - 1]) || (m[s] == m[s - 1] && id[s] < id[s - 1]);
            if (b) {
                float tv = m[s]; m[s] = m[s - 1]; m[s - 1] = tv;
                int ti = id[s]; id[s] = id[s - 1]; id[s - 1] = ti;
            }
        }
    }
}

// ---------------------------------------------------------------------------
// K1: bf16 wmma screen. CTA = 128 tokens x 64 experts. 8 warps; warp w owns
// token-tile w (16 tokens) x all 4 expert-tiles. Approx logits -> top-8 ids.
// ---------------------------------------------------------------------------
__global__ void __launch_bounds__(TPBA)
screen_kernel(const float* __restrict__ x, const float* __restrict__ W, int N) {
    extern __shared__ char sm[];
    __nv_bfloat16* A_s = (__nv_bfloat16*)sm;                      // 128*72*2
    __nv_bfloat16* B_s = (__nv_bfloat16*)(sm + TOKA * SA * 2);    // 64*72*2
    float* L_s = (float*)sm;                                      // overlay

    const int tid = threadIdx.x;
    const int warp = tid >> 5;

    wmma::fragment<wmma::accumulator, 16, 16, 16, float> acc[4];
#pragma unroll
    for (int et = 0; et < 4; ++et) wmma::fill_fragment(acc[et], 0.0f);

    for (int kc = 0; kc < HD / CKA; ++kc) {
        __syncthreads();
        // x chunk: 128 tok x 64 k fp32 -> bf16 A_s
#pragma unroll
        for (int i = 0; i < 8; ++i) {
            int idx = tid + i * TPBA;
            int tk = idx >> 4, q = idx & 15;
            int gr = min(blockIdx.x * TOKA + tk, N - 1);
            float4 v = *(const float4*)(x + (size_t)gr * HD + kc * CKA + q * 4);
            __nv_bfloat162* d = (__nv_bfloat162*)&A_s[tk * SA + q * 4];
            d[0] = __floats2bfloat162_rn(v.x, v.y);
            d[1] = __floats2bfloat162_rn(v.z, v.w);
        }
        // W chunk: 64 k x 64 e fp32 -> bf16 B_s
#pragma unroll
        for (int i = 0; i < 16; ++i) {
            int idx = tid + i * TPBA;
            int k = idx >> 6, e = idx & 63;
            B_s[k * SB + e] = __float2bfloat16(W[(kc * CKA + k) * NE + e]);
        }
        __syncthreads();

#pragma unroll
        for (int kk = 0; kk < 4; ++kk) {
            wmma::fragment<wmma::matrix_a, 16, 16, 16, __nv_bfloat16,
                           wmma::row_major> af;
            wmma::load_matrix_sync(af, A_s + (warp * 16) * SA + kk * 16, SA);
#pragma unroll
            for (int et = 0; et < 4; ++et) {
                wmma::fragment<wmma::matrix_b, 16, 16, 16, __nv_bfloat16,
                               wmma::row_major> bf;
                wmma::load_matrix_sync(bf, B_s + (kk * 16) * SB + et * 16, SB);
                wmma::mma_sync(acc[et], af, bf, acc[et]);
            }
        }
    }
    __syncthreads();
#pragma unroll
    for (int et = 0; et < 4; ++et)
        wmma::store_matrix_sync(L_s + (warp * 16) * SL + et * 16, acc[et], SL,
                                wmma::mem_row_major);
    __syncthreads();

    if (tid < TOKA) {
        float m[8]; int id[8];
#pragma unroll
        for (int s = 0; s < 8; ++s) { m[s] = -1e30f; id[s] = NE; }
#pragma unroll
        for (int q = 0; q < 16; ++q) {
            float4 v = *(const float4*)(L_s + tid * SL + q * 4);
            ins8(v.x, q * 4 + 0, m, id);
            ins8(v.y, q * 4 + 1, m, id);
            ins8(v.z, q * 4 + 2, m, id);
            ins8(v.w, q * 4 + 3, m, id);
        }
        int gt = blockIdx.x * TOKA + tid;
        if (gt < N) {
            uint2 r;
            r.x = (unsigned)id[0] | ((unsigned)id[1] << 8) |
                  ((unsigned)id[2] << 16) | ((unsigned)id[3] << 24);
            r.y = (unsigned)id[4] | ((unsigned)id[5] << 8) |
                  ((unsigned)id[6] << 16) | ((unsigned)id[7] << 24);
            *(uint2*)(g_cand + (size_t)gt * 8) = r;
        }
    }
}

// ---------------------------------------------------------------------------
// K2: exact rescue. CTA = 64 tokens x 8 candidates. Double-buffered cp.async
// staging of x rows and W^T rows; per-thread scalar fp32 fma chain over k
// ascending 0..1023 (bit-identical to the full exact computation). Then top-2
// among candidates (strict >, lower id on ties), weights, block histogram.
// ---------------------------------------------------------------------------
__global__ void __launch_bounds__(TPBR)
rescue_kernel(const float* __restrict__ x, float* __restrict__ f_idx,
              float* __restrict__ f_w, int N) {
    extern __shared__ char sm[];
    float* xs = (float*)sm;                              // [2][TOKR*XBS]
    float* ws = (float*)(sm + 2 * TOKR * XBS * 4);       // [2][NE*XBS]
    __shared__ int h[NE];

    const int tid = threadIdx.x;
    const int tok = tid >> 3, c = tid & 7;
    const int gt = blockIdx.x * TOKR + tok;
    const int gtc = min(gt, N - 1);
    const int cid = g_cand[(size_t)gtc * 8 + c];

    // staging: idx = tid + i*512 -> row = idx>>5 (0..63), q = idx&31
    const int srow = tid >> 5;
    const int sq = tid & 31;
    const int grow = min(blockIdx.x * TOKR + ((tid % 512) >> 5), N - 1);

    float acc = 0.0f;

    // prologue: chunk 0 -> buffer 0
    {
        int xr = min(blockIdx.x * TOKR + srow, N - 1); (void)grow;
#pragma unroll
        for (int i = 0; i < 4; ++i) {
            int idx = tid + i * TPBR;
            int row = idx >> 5, q = idx & 31;
            int gr = min(blockIdx.x * TOKR + row, N - 1);
            cp_async16(xs + row * XBS + q * 4, x + (size_t)gr * HD + q * 4);
            cp_async16(ws + row * XBS + q * 4, g_WT + row * HD + q * 4);
        }
        (void)xr; (void)sq;
        CP_COMMIT();
    }

    for (int ch = 0; ch < NCHB; ++ch) {
        const int b = ch & 1;
        if (ch + 1 < NCHB) {
            float* xnb = xs + (1 - b) * TOKR * XBS;
            float* wnb = ws + (1 - b) * NE * XBS;
#pragma unroll
            for (int i = 0; i < 4; ++i) {
                int idx = tid + i * TPBR;
                int row = idx >> 5, q = idx & 31;
                int gr = min(blockIdx.x * TOKR + row, N - 1);
                cp_async16(xnb + row * XBS + q * 4,
                           x + (size_t)gr * HD + (ch + 1) * CKB + q * 4);
                cp_async16(wnb + row * XBS + q * 4,
                           g_WT + row * HD + (ch + 1) * CKB + q * 4);
            }
            CP_COMMIT();
            CP_WAIT1();
        } else {
            CP_WAIT0();
        }
        __syncthreads();

        const float* xr = xs + b * TOKR * XBS + tok * XBS;
        const float* wr = ws + b * NE * XBS + cid * XBS;
#pragma unroll
        for (int kg = 0; kg < CKB / 4; ++kg) {
            float4 xv = *(const float4*)(xr + kg * 4);
            float4 wv = *(const float4*)(wr + kg * 4);
            acc = fmaf(xv.x, wv.x, acc);
            acc = fmaf(xv.y, wv.y, acc);
            acc = fmaf(xv.z, wv.z, acc);
            acc = fmaf(xv.w, wv.w, acc);
        }
        __syncthreads();
    }

    // exchange: exact candidate logits + ids
    float* exv = xs;
    int* exi = (int*)ws;
    exv[tok * 8 + c] = acc;
    exi[tok * 8 + c] = cid;
    if (tid < NE) h[tid] = 0;
    __syncthreads();

    if (tid < TOKR) {
        float m0 = -1e30f, m1 = -1e30f;
        int i0 = NE, i1 = NE;
#pragma unroll
        for (int cc = 0; cc < 8; ++cc) {
            float v = exv[tid * 8 + cc];
            int j = exi[tid * 8 + cc];
            if (v > m0 || (v == m0 && j < i0)) { m1 = m0; i1 = i0; m0 = v; i0 = j; }
            else if (v > m1 || (v == m1 && j < i1)) { m1 = v; i1 = j; }
        }
        int g = blockIdx.x * TOKR + tid;
        if (g < N) {
            float tE = expf(m1 - m0);
            float s0 = 1.0f / (1.0f + tE);
            f_idx[2 * g]     = (float)i0;
            f_idx[2 * g + 1] = (float)i1;
            f_w[2 * g]       = s0;
            f_w[2 * g + 1]   = tE * s0;
            atomicAdd(&h[i0], 1);
            atomicAdd(&h[i1], 1);
        }
    }
    __syncthreads();
    if (tid < NE) g_hist[blockIdx.x * NE + tid] = h[tid];
}

// ---------------------------------------------------------------------------
// K3: per-expert exclusive scan across rescue blocks.
// ---------------------------------------------------------------------------
__global__ void scan_kernel(float* __restrict__ out_cnt, int capacity, int NB) {
    int e = blockIdx.x;
    int t = threadIdx.x;    // 256
    __shared__ int ssum[256];
    int P = (NB + 255) >> 8;
    int s = t * P, eidx = min(NB, s + P);
    int sum = 0;
    for (int b = s; b < eidx; ++b) sum += g_hist[b * NE + e];
    ssum[t] = sum;
    __syncthreads();
    for (int off = 1; off < 256; off <<= 1) {
        int u = (t >= off) ? ssum[t - off] : 0;
        __syncthreads();
        ssum[t] += u;
        __syncthreads();
    }
    int run = ssum[t] - sum;
    for (int b = s; b < eidx; ++b) {
        g_base[b * NE + e] = run;
        run += g_hist[b * NE + e];
    }
    if (t == 255) {
        int total = ssum[255];
        out_cnt[e] = (float)min(total, capacity);
        g_edrop[e] = max(0, total - capacity);
    }
}

// ---------------------------------------------------------------------------
// K4: ordered capacity mask + weight normalization (1 warp / rescue block).
// ---------------------------------------------------------------------------
__global__ void mask_kernel(const float* __restrict__ idxf, float* __restrict__ wf,
                            float* __restrict__ maskf, float* __restrict__ dropf,
                            int capacity, int flat) {
    int b = blockIdx.x;
    int lane = threadIdx.x;
    if (b == 0 && lane == 0) {
        int tot = 0;
        for (int i = 0; i < NE; ++i) tot += g_edrop[i];
        dropf[0] = (float)tot;
    }
    __shared__ int sc[NE];
    for (int e = lane; e < NE; e += 32) sc[e] = g_base[b * NE + e];
    __syncwarp();

    int s = b * (TOKR * TOPK);
    int e_ = min(flat, s + TOKR * TOPK);
    for (int i0 = s; i0 < e_; i0 += 32) {
        int i = i0 + lane;
        bool valid = (i < e_);
        unsigned am = __ballot_sync(0xffffffffu, valid);
        float m = 0.f, w = 0.f;
        if (valid) {
            int ex = (int)idxf[i];
            unsigned grp = __match_any_sync(am, ex);
            int leader = __ffs(grp) - 1;
            int prior = __popc(grp & ((1u << lane) - 1u));
            int base = 0;
            if (lane == leader) {
                base = sc[ex];
                sc[ex] = base + __popc(grp);
            }
            base = __shfl_sync(am, base, leader);
            int pos = base + prior;
            m = (pos < capacity) ? 1.f : 0.f;
            w = wf[i];
        }
        float mo = __shfl_xor_sync(0xffffffffu, m, 1);
        if (valid) {
            float msum = m + mo;
            maskf[i] = m;
            wf[i] = w * m / (msum + 1e-10f);
        }
        __syncwarp();
    }
}

// ---------------------------------------------------------------------------
extern "C" void kernel_launch(void* const* d_in, const int* in_sizes, int n_in,
                              void* d_out, int out_size) {
    const float* x = (const float*)d_in[0];
    const float* W = (const float*)d_in[1];
    if (n_in >= 2 && in_sizes[0] < in_sizes[1]) {
        const float* tmp = x; x = W; W = tmp;
    }
    int N = ((in_sizes[0] >= in_sizes[1]) ? in_sizes[0] : in_sizes[1]) / HD;
    int flat = N * TOPK;
    int NBA = (N + TOKA - 1) / TOKA;
    int NBR = (N + TOKR - 1) / TOKR;

    float* out    = (float*)d_out;
    float* f_idx  = out;
    float* f_w    = out + flat;
    float* f_mask = out + 2 * flat;
    float* f_cnt  = out + 3 * flat;
    float* f_drop = f_cnt + NE;

    int capacity = (int)(((double)N * (double)TOPK / (double)NE) * 1.25);

    int smA = TOKA * SL * 4;                         // 34816 (covers A_s+B_s too)
    if (smA < TOKA * SA * 2 + CKA * SB * 2) smA = TOKA * SA * 2 + CKA * SB * 2;
    int smR = (2 * TOKR * XBS + 2 * NE * XBS) * 4;   // 135168

    cudaFuncSetAttribute(screen_kernel,
                         cudaFuncAttributeMaxDynamicSharedMemorySize, smA);
    cudaFuncSetAttribute(rescue_kernel,
                         cudaFuncAttributeMaxDynamicSharedMemorySize, smR);

    wt_kernel<<<NE, 256>>>(W);
    screen_kernel<<<NBA, TPBA, smA>>>(x, W, N);
    rescue_kernel<<<NBR, TPBR, smR>>>(x, f_idx, f_w, N);
    scan_kernel<<<NE, 256>>>(f_cnt, capacity, NBR);
    mask_kernel<<<NBR, 32>>>(f_idx, f_w, f_mask, f_drop, capacity, flat);
}

// round 9
// speedup vs baseline: 1.2245x; 1.2245x over previous
#include <cuda_runtime.h>
#include <cuda_bf16.h>
#include <mma.h>
#include <cstdint>
#include <math.h>

// ----------------------------------------------------------------------------
// CapacityRouter = bf16 wmma screen (top-8 candidates, zero-miss proven R6)
//                + exact fp32 rescue (bit-identical selection/weights)
// Output: [ idx (N*2) | w (N*2) | mask (N*2) | counters (64) | dropped (1) ]
// ----------------------------------------------------------------------------

#define HD 1024
#define NE 64
#define TOPK 2
#define MAXN (1 << 18)
#define MAXB 8192

// screen
#define TOKA 128
#define TPBA 256
#define CKA 64
#define SA 72          // A_s stride (bf16 elems) = 144 B
#define SBst 72        // B_s stride (bf16 elems) = 144 B
#define SL 68          // logits stride (f32)

// rescue
#define TOKR 128
#define TPBR 128
#define CKB 32
#define WST 36         // smem row stride (floats) = 144 B
#define NCHB (HD / CKB)

__device__ unsigned char g_cand[(size_t)MAXN * 8];
__device__ float g_WT[NE * HD];                 // fp32 W^T [e][k] (rescue)
__device__ __nv_bfloat16 g_Wbf[HD * NE];        // bf16 W [k][e] (screen B)
__device__ int g_hist[MAXB * NE];
__device__ int g_base[MAXB * NE];
__device__ int g_edrop[NE];

using namespace nvcuda;

__device__ __forceinline__ void cp_async16(void* smem_dst, const void* gmem_src) {
    unsigned s = (unsigned)__cvta_generic_to_shared(smem_dst);
    asm volatile("cp.async.ca.shared.global [%0], [%1], 16;\n"
                 :: "r"(s), "l"(gmem_src));
}
#define CP_COMMIT() asm volatile("cp.async.commit_group;\n" ::: "memory")
#define CP_WAIT1()  asm volatile("cp.async.wait_group 1;\n" ::: "memory")
#define CP_WAIT0()  asm volatile("cp.async.wait_group 0;\n" ::: "memory")

// ---------------------------------------------------------------------------
// K0: W^T fp32 (rescue) + bf16 W [k][e] (screen).
// ---------------------------------------------------------------------------
__global__ void wt_kernel(const float* __restrict__ W) {
    int e = blockIdx.x;
    for (int k = threadIdx.x; k < HD; k += blockDim.x) {
        float v = W[k * NE + e];
        g_WT[e * HD + k] = v;
        g_Wbf[k * NE + e] = __float2bfloat16(v);
    }
}

// sorted-8 insertion (descending value, ascending id on ties)
__device__ __forceinline__ void ins8(float v, int j, float* m, int* id) {
    if ((v > m[7]) || (v == m[7] && j < id[7])) {
        m[7] = v; id[7] = j;
#pragma unroll
        for (int s = 7; s > 0; --s) {
            bool b = (m[s] > m[s - 1]) || (m[s] == m[s - 1] && id[s] < id[s - 1]);
            if (b) {
                float tv = m[s]; m[s] = m[s - 1]; m[s - 1] = tv;
                int ti = id[s]; id[s] = id[s - 1]; id[s - 1] = ti;
            }
        }
    }
}

// ---------------------------------------------------------------------------
// K1: bf16 wmma screen, double-buffered. CTA = 128 tokens x 64 experts.
// 8 warps; warp w = token tile w (16 tokens) x all 4 expert tiles.
// A: LDG->regs (next chunk) overlapped with compute; converted + STS.
// B: cp.async plain copy of pre-converted bf16 tiles into stride-144 rows.
// ---------------------------------------------------------------------------
__global__ void __launch_bounds__(TPBA)
screen_kernel(const float* __restrict__ x, int N) {
    extern __shared__ char sm[];
    __nv_bfloat16* A_s = (__nv_bfloat16*)sm;                     // 2 x 128*72
    __nv_bfloat16* B_s = (__nv_bfloat16*)(sm + 2 * TOKA * SA * 2); // 2 x 64*72
    float* L_s = (float*)sm;                                     // overlay

    const int tid = threadIdx.x;
    const int warp = tid >> 5;

    wmma::fragment<wmma::accumulator, 16, 16, 16, float> acc[4];
#pragma unroll
    for (int et = 0; et < 4; ++et) wmma::fill_fragment(acc[et], 0.0f);

    // A prefetch registers (8 float4 = 32 fp32 = this thread's staging share)
    float4 xr[8];
#pragma unroll
    for (int i = 0; i < 8; ++i) {
        int idx = tid + i * TPBA;
        int row = idx >> 4, q = idx & 15;
        int gr = min(blockIdx.x * TOKA + row, N - 1);
        xr[i] = *(const float4*)(x + (size_t)gr * HD + q * 4);
    }
    // B chunk 0 via cp.async (512 x 16B pieces -> 2 per thread)
#pragma unroll
    for (int i = 0; i < 2; ++i) {
        int p = tid + i * TPBA;
        int row = p >> 3, piece = p & 7;
        cp_async16((char*)B_s + row * 144 + piece * 16,
                   (const char*)g_Wbf + (size_t)row * 128 + piece * 16);
    }
    CP_COMMIT();

    for (int c = 0; c < HD / CKA; ++c) {
        const int b = c & 1;
        __nv_bfloat16* Ab = A_s + b * TOKA * SA;
        __nv_bfloat16* Bb = B_s + b * CKA * SBst;

        // STS A_c (convert fp32 regs -> bf16 smem)
#pragma unroll
        for (int i = 0; i < 8; ++i) {
            int idx = tid + i * TPBA;
            int row = idx >> 4, q = idx & 15;
            __nv_bfloat162 p0 = __floats2bfloat162_rn(xr[i].x, xr[i].y);
            __nv_bfloat162 p1 = __floats2bfloat162_rn(xr[i].z, xr[i].w);
            uint2 pk;
            pk.x = *reinterpret_cast<unsigned*>(&p0);
            pk.y = *reinterpret_cast<unsigned*>(&p1);
            *(uint2*)((char*)Ab + row * 144 + q * 8) = pk;
        }
        if (c + 1 < HD / CKA) {
            // prefetch A_{c+1} -> regs
#pragma unroll
            for (int i = 0; i < 8; ++i) {
                int idx = tid + i * TPBA;
                int row = idx >> 4, q = idx & 15;
                int gr = min(blockIdx.x * TOKA + row, N - 1);
                xr[i] = *(const float4*)(x + (size_t)gr * HD + (c + 1) * CKA + q * 4);
            }
            // prefetch B_{c+1} -> other buffer
            __nv_bfloat16* Bn = B_s + (1 - b) * CKA * SBst;
#pragma unroll
            for (int i = 0; i < 2; ++i) {
                int p = tid + i * TPBA;
                int row = p >> 3, piece = p & 7;
                cp_async16((char*)Bn + row * 144 + piece * 16,
                           (const char*)g_Wbf + ((size_t)(c + 1) * CKA + row) * 128
                               + piece * 16);
            }
            CP_COMMIT();
            CP_WAIT1();   // B_c drained, B_{c+1} in flight
        } else {
            CP_WAIT0();
        }
        __syncthreads();

#pragma unroll
        for (int kk = 0; kk < 4; ++kk) {
            wmma::fragment<wmma::matrix_a, 16, 16, 16, __nv_bfloat16,
                           wmma::row_major> af;
            wmma::load_matrix_sync(af, Ab + (warp * 16) * SA + kk * 16, SA);
#pragma unroll
            for (int et = 0; et < 4; ++et) {
                wmma::fragment<wmma::matrix_b, 16, 16, 16, __nv_bfloat16,
                               wmma::row_major> bf;
                wmma::load_matrix_sync(bf, Bb + (kk * 16) * SBst + et * 16, SBst);
                wmma::mma_sync(acc[et], af, bf, acc[et]);
            }
        }
        __syncthreads();
    }

    // logits -> smem overlay -> per-token top-8 (identical to proven R6 code)
#pragma unroll
    for (int et = 0; et < 4; ++et)
        wmma::store_matrix_sync(L_s + (warp * 16) * SL + et * 16, acc[et], SL,
                                wmma::mem_row_major);
    __syncthreads();

    if (tid < TOKA) {
        float m[8]; int id[8];
#pragma unroll
        for (int s = 0; s < 8; ++s) { m[s] = -1e30f; id[s] = NE; }
#pragma unroll
        for (int q = 0; q < 16; ++q) {
            float4 v = *(const float4*)(L_s + tid * SL + q * 4);
            ins8(v.x, q * 4 + 0, m, id);
            ins8(v.y, q * 4 + 1, m, id);
            ins8(v.z, q * 4 + 2, m, id);
            ins8(v.w, q * 4 + 3, m, id);
        }
        int gt = blockIdx.x * TOKA + tid;
        if (gt < N) {
            uint2 r;
            r.x = (unsigned)id[0] | ((unsigned)id[1] << 8) |
                  ((unsigned)id[2] << 16) | ((unsigned)id[3] << 24);
            r.y = (unsigned)id[4] | ((unsigned)id[5] << 8) |
                  ((unsigned)id[6] << 16) | ((unsigned)id[7] << 24);
            *(uint2*)(g_cand + (size_t)gt * 8) = r;
        }
    }
}

// ---------------------------------------------------------------------------
// K2: exact rescue. Thread = TOKEN, acc[8] candidate chains (x read once).
// Sequential-k fp32 fma chains bit-identical to the full exact computation.
// ---------------------------------------------------------------------------
__global__ void __launch_bounds__(TPBR, 4)
rescue_kernel(const float* __restrict__ x, float* __restrict__ f_idx,
              float* __restrict__ f_w, int N) {
    extern __shared__ float smf[];
    float* xs = smf;                          // 2 x TOKR*WST
    float* ws = smf + 2 * TOKR * WST;         // 2 x NE*WST
    __shared__ int h[NE];

    const int tid = threadIdx.x;
    const int gt = blockIdx.x * TOKR + tid;
    const int gtc = min(gt, N - 1);

    uint2 cw = *(const uint2*)(g_cand + (size_t)gtc * 8);
    int cid[8];
#pragma unroll
    for (int j = 0; j < 4; ++j) cid[j] = (cw.x >> (8 * j)) & 0xff;
#pragma unroll
    for (int j = 0; j < 4; ++j) cid[4 + j] = (cw.y >> (8 * j)) & 0xff;

    float acc[8];
#pragma unroll
    for (int j = 0; j < 8; ++j) acc[j] = 0.0f;

    // prologue: chunk 0 -> buffer 0
#pragma unroll
    for (int i = 0; i < 8; ++i) {
        int idx = tid + i * TPBR;
        int row = idx >> 3, q = idx & 7;
        int gr = min(blockIdx.x * TOKR + row, N - 1);
        cp_async16(xs + row * WST + q * 4, x + (size_t)gr * HD + q * 4);
    }
#pragma unroll
    for (int i = 0; i < 4; ++i) {
        int idx = tid + i * TPBR;
        int row = idx >> 3, q = idx & 7;
        cp_async16(ws + row * WST + q * 4, g_WT + (size_t)row * HD + q * 4);
    }
    CP_COMMIT();

    for (int ch = 0; ch < NCHB; ++ch) {
        const int b = ch & 1;
        if (ch + 1 < NCHB) {
            float* xn = xs + (1 - b) * TOKR * WST;
            float* wn = ws + (1 - b) * NE * WST;
#pragma unroll
            for (int i = 0; i < 8; ++i) {
                int idx = tid + i * TPBR;
                int row = idx >> 3, q = idx & 7;
                int gr = min(blockIdx.x * TOKR + row, N - 1);
                cp_async16(xn + row * WST + q * 4,
                           x + (size_t)gr * HD + (ch + 1) * CKB + q * 4);
            }
#pragma unroll
            for (int i = 0; i < 4; ++i) {
                int idx = tid + i * TPBR;
                int row = idx >> 3, q = idx & 7;
                cp_async16(wn + row * WST + q * 4,
                           g_WT + (size_t)row * HD + (ch + 1) * CKB + q * 4);
            }
            CP_COMMIT();
            CP_WAIT1();
        } else {
            CP_WAIT0();
        }
        __syncthreads();

        const float* xr = xs + b * TOKR * WST + tid * WST;
        const float* wb = ws + b * NE * WST;
#pragma unroll
        for (int kg = 0; kg < CKB / 4; ++kg) {
            float4 xv = *(const float4*)(xr + kg * 4);
#pragma unroll
            for (int j = 0; j < 8; ++j) {
                float4 wv = *(const float4*)(wb + cid[j] * WST + kg * 4);
                float a = acc[j];
                a = fmaf(xv.x, wv.x, a);
                a = fmaf(xv.y, wv.y, a);
                a = fmaf(xv.z, wv.z, a);
                a = fmaf(xv.w, wv.w, a);
                acc[j] = a;
            }
        }
        __syncthreads();   // protect buffer reuse by next chunk's cp.async
    }

    // top-2 among the 8 exact candidate logits (strict >, lower id on ties)
    if (tid < NE) h[tid] = 0;
    __syncthreads();
    {
        float m0 = -1e30f, m1 = -1e30f;
        int i0 = NE, i1 = NE;
#pragma unroll
        for (int j = 0; j < 8; ++j) {
            float v = acc[j];
            int jd = cid[j];
            if (v > m0 || (v == m0 && jd < i0)) { m1 = m0; i1 = i0; m0 = v; i0 = jd; }
            else if (v > m1 || (v == m1 && jd < i1)) { m1 = v; i1 = jd; }
        }
        if (gt < N) {
            float tE = expf(m1 - m0);
            float s0 = 1.0f / (1.0f + tE);
            f_idx[2 * gt]     = (float)i0;
            f_idx[2 * gt + 1] = (float)i1;
            f_w[2 * gt]       = s0;
            f_w[2 * gt + 1]   = tE * s0;
            atomicAdd(&h[i0], 1);
            atomicAdd(&h[i1], 1);
        }
    }
    __syncthreads();
    if (tid < NE) g_hist[blockIdx.x * NE + tid] = h[tid];
}

// ---------------------------------------------------------------------------
// K3: per-expert exclusive scan across rescue blocks.
// ---------------------------------------------------------------------------
__global__ void scan_kernel(float* __restrict__ out_cnt, int capacity, int NB) {
    int e = blockIdx.x;
    int t = threadIdx.x;    // 256
    __shared__ int ssum[256];
    int P = (NB + 255) >> 8;
    int s = t * P, eidx = min(NB, s + P);
    int sum = 0;
    for (int b = s; b < eidx; ++b) sum += g_hist[b * NE + e];
    ssum[t] = sum;
    __syncthreads();
    for (int off = 1; off < 256; off <<= 1) {
        int u = (t >= off) ? ssum[t - off] : 0;
        __syncthreads();
        ssum[t] += u;
        __syncthreads();
    }
    int run = ssum[t] - sum;
    for (int b = s; b < eidx; ++b) {
        g_base[b * NE + e] = run;
        run += g_hist[b * NE + e];
    }
    if (t == 255) {
        int total = ssum[255];
        out_cnt[e] = (float)min(total, capacity);
        g_edrop[e] = max(0, total - capacity);
    }
}

// ---------------------------------------------------------------------------
// K4: ordered capacity mask + weight normalization (1 warp / rescue block).
// ---------------------------------------------------------------------------
__global__ void mask_kernel(const float* __restrict__ idxf, float* __restrict__ wf,
                            float* __restrict__ maskf, float* __restrict__ dropf,
                            int capacity, int flat) {
    int b = blockIdx.x;
    int lane = threadIdx.x;
    if (b == 0 && lane == 0) {
        int tot = 0;
        for (int i = 0; i < NE; ++i) tot += g_edrop[i];
        dropf[0] = (float)tot;
    }
    __shared__ int sc[NE];
    for (int e = lane; e < NE; e += 32) sc[e] = g_base[b * NE + e];
    __syncwarp();

    int s = b * (TOKR * TOPK);
    int e_ = min(flat, s + TOKR * TOPK);
    for (int i0 = s; i0 < e_; i0 += 32) {
        int i = i0 + lane;
        bool valid = (i < e_);
        unsigned am = __ballot_sync(0xffffffffu, valid);
        float m = 0.f, w = 0.f;
        if (valid) {
            int ex = (int)idxf[i];
            unsigned grp = __match_any_sync(am, ex);
            int leader = __ffs(grp) - 1;
            int prior = __popc(grp & ((1u << lane) - 1u));
            int base = 0;
            if (lane == leader) {
                base = sc[ex];
                sc[ex] = base + __popc(grp);
            }
            base = __shfl_sync(am, base, leader);
            int pos = base + prior;
            m = (pos < capacity) ? 1.f : 0.f;
            w = wf[i];
        }
        float mo = __shfl_xor_sync(0xffffffffu, m, 1);
        if (valid) {
            float msum = m + mo;
            maskf[i] = m;
            wf[i] = w * m / (msum + 1e-10f);
        }
        __syncwarp();
    }
}

// ---------------------------------------------------------------------------
extern "C" void kernel_launch(void* const* d_in, const int* in_sizes, int n_in,
                              void* d_out, int out_size) {
    const float* x = (const float*)d_in[0];
    const float* W = (const float*)d_in[1];
    if (n_in >= 2 && in_sizes[0] < in_sizes[1]) {
        const float* tmp = x; x = W; W = tmp;
    }
    int N = ((in_sizes[0] >= in_sizes[1]) ? in_sizes[0] : in_sizes[1]) / HD;
    int flat = N * TOPK;
    int NBS = (N + TOKA - 1) / TOKA;
    int NBR = (N + TOKR - 1) / TOKR;

    float* out    = (float*)d_out;
    float* f_idx  = out;
    float* f_w    = out + flat;
    float* f_mask = out + 2 * flat;
    float* f_cnt  = out + 3 * flat;
    float* f_drop = f_cnt + NE;

    int capacity = (int)(((double)N * (double)TOPK / (double)NE) * 1.25);

    int smS = 2 * TOKA * SA * 2 + 2 * CKA * SBst * 2;    // 55296
    if (smS < TOKA * SL * 4) smS = TOKA * SL * 4;
    int smR = (2 * TOKR * WST + 2 * NE * WST) * 4;       // 55296

    cudaFuncSetAttribute(screen_kernel,
                         cudaFuncAttributeMaxDynamicSharedMemorySize, smS);
    cudaFuncSetAttribute(rescue_kernel,
                         cudaFuncAttributeMaxDynamicSharedMemorySize, smR);

    wt_kernel<<<NE, 256>>>(W);
    screen_kernel<<<NBS, TPBA, smS>>>(x, N);
    rescue_kernel<<<NBR, TPBR, smR>>>(x, f_idx, f_w, N);
    scan_kernel<<<NE, 256>>>(f_cnt, capacity, NBR);
    mask_kernel<<<NBR, 32>>>(f_idx, f_w, f_mask, f_drop, capacity, flat);
}

// round 11
// speedup vs baseline: 1.6729x; 1.3662x over previous
#include <cuda_runtime.h>
#include <cuda_bf16.h>
#include <mma.h>
#include <cstdint>
#include <math.h>

// ----------------------------------------------------------------------------
// CapacityRouter = split-bf16 (3-pass) wmma screen with near-fp32 logits
// (finalizes high-margin tokens incl. weights) + exact fp32 rescue of the
// ~0.5% ambiguous tokens (top-8 candidates, sequential-k bit-exact chains).
// Output: [ idx (N*2) | w (N*2) | mask (N*2) | counters (64) | dropped (1) ]
// ----------------------------------------------------------------------------

#define HD 1024
#define NE 64
#define TOPK 2
#define MAXN (1 << 18)
#define MAXB 8192
#define T_MARGIN 2e-3f

// screen
#define TOKA 128
#define TPBA 256
#define CKA 64
#define SA 72          // A_s stride (bf16) = 144 B
#define SBst 72        // B_s stride (bf16) = 144 B
#define SL 68          // logits stride (f32)

// rescue
#define TPBR 128
#define CKB 32
#define WST 36         // smem row stride (floats) = 144 B
#define NCHB (HD / CKB)   // 32

struct QEnt { int tok; unsigned c0, c1; int pad; };

__device__ QEnt g_queue[MAXN];
__device__ int g_qcount;
__device__ float g_WT[NE * HD];                // fp32 W^T [e][k]
__device__ __nv_bfloat16 g_Wbf[2 * HD * NE];   // plane0 = hi, plane1 = lo
__device__ int g_hist[MAXB * NE];
__device__ int g_base[MAXB * NE];
__device__ int g_edrop[NE];

using namespace nvcuda;

__device__ __forceinline__ void cp_async16(void* smem_dst, const void* gmem_src) {
    unsigned s = (unsigned)__cvta_generic_to_shared(smem_dst);
    asm volatile("cp.async.ca.shared.global [%0], [%1], 16;\n"
                 :: "r"(s), "l"(gmem_src));
}
#define CP_COMMIT() asm volatile("cp.async.commit_group;\n" ::: "memory")
#define CP_WAIT1()  asm volatile("cp.async.wait_group 1;\n" ::: "memory")
#define CP_WAIT0()  asm volatile("cp.async.wait_group 0;\n" ::: "memory")

// ---------------------------------------------------------------------------
// K0: W^T fp32 (rescue) + bf16 hi/lo planes of W [k][e] (screen B).
// ---------------------------------------------------------------------------
__global__ void wt_kernel(const float* __restrict__ W) {
    int e = blockIdx.x;
    if (e == 0 && threadIdx.x == 0) g_qcount = 0;
    for (int k = threadIdx.x; k < HD; k += blockDim.x) {
        float v = W[k * NE + e];
        g_WT[e * HD + k] = v;
        __nv_bfloat16 hi = __float2bfloat16(v);
        float lo = v - __bfloat162float(hi);
        g_Wbf[k * NE + e] = hi;
        g_Wbf[HD * NE + k * NE + e] = __float2bfloat16(lo);
    }
}

// sorted-8 insertion (descending value, ascending id on ties)
__device__ __forceinline__ void ins8(float v, int j, float* m, int* id) {
    if ((v > m[7]) || (v == m[7] && j < id[7])) {
        m[7] = v; id[7] = j;
#pragma unroll
        for (int s = 7; s > 0; --s) {
            bool b = (m[s] > m[s - 1]) || (m[s] == m[s - 1] && id[s] < id[s - 1]);
            if (b) {
                float tv = m[s]; m[s] = m[s - 1]; m[s - 1] = tv;
                int ti = id[s]; id[s] = id[s - 1]; id[s - 1] = ti;
            }
        }
    }
}

// ---------------------------------------------------------------------------
// K1: split-bf16 wmma screen. CTA = 128 tokens x 64 experts.
// acc += Ahi*Bhi + Ahi*Blo + Alo*Bhi  (fp32 accum) -> logit err ~1e-5.
// High-margin (2e-3) tokens finalized (idx + weights); ambiguous queued.
// ---------------------------------------------------------------------------
__global__ void __launch_bounds__(TPBA, 2)
screen_kernel(const float* __restrict__ x, float* __restrict__ f_idx,
              float* __restrict__ f_w, int N) {
    extern __shared__ char sm[];
    // A: [buf][plane][128][SA] bf16 ; B: [buf][plane][64][SBst] bf16
    __nv_bfloat16* A_s = (__nv_bfloat16*)sm;
    __nv_bfloat16* B_s = (__nv_bfloat16*)(sm + 4 * TOKA * SA * 2);
    float* L_s = (float*)sm;   // overlay after mainloop

    __shared__ int h[NE];
    __shared__ int qn, qb;

    const int tid = threadIdx.x;
    const int warp = tid >> 5;

    wmma::fragment<wmma::accumulator, 16, 16, 16, float> acc[4];
#pragma unroll
    for (int et = 0; et < 4; ++et) wmma::fill_fragment(acc[et], 0.0f);

    // prologue: A0 -> regs; B0 (both planes) -> buf0
    float4 xr[8];
#pragma unroll
    for (int i = 0; i < 8; ++i) {
        int idx = tid + i * TPBA;
        int row = idx >> 4, q = idx & 15;
        int gr = min(blockIdx.x * TOKA + row, N - 1);
        xr[i] = *(const float4*)(x + (size_t)gr * HD + q * 4);
    }
#pragma unroll
    for (int p = 0; p < 2; ++p)
#pragma unroll
        for (int i = 0; i < 2; ++i) {
            int pp = tid + i * TPBA;
            int row = pp >> 3, piece = pp & 7;
            cp_async16((char*)(B_s + p * CKA * SBst) + row * 144 + piece * 16,
                       (const char*)(g_Wbf + p * HD * NE) + (size_t)row * 128
                           + piece * 16);
        }
    CP_COMMIT();

    for (int c = 0; c < HD / CKA; ++c) {
        const int b = c & 1;
        __nv_bfloat16* Ah = A_s + (b * 2 + 0) * TOKA * SA;
        __nv_bfloat16* Al = A_s + (b * 2 + 1) * TOKA * SA;
        __nv_bfloat16* Bh = B_s + (b * 2 + 0) * CKA * SBst;
        __nv_bfloat16* Bl = B_s + (b * 2 + 1) * CKA * SBst;

        // STS A_c: split fp32 regs into hi/lo bf16 planes
#pragma unroll
        for (int i = 0; i < 8; ++i) {
            int idx = tid + i * TPBA;
            int row = idx >> 4, q = idx & 15;
            float a0 = xr[i].x, a1 = xr[i].y, a2 = xr[i].z, a3 = xr[i].w;
            __nv_bfloat16 h0 = __float2bfloat16(a0), h1 = __float2bfloat16(a1);
            __nv_bfloat16 h2 = __float2bfloat16(a2), h3 = __float2bfloat16(a3);
            __nv_bfloat162 ph0; ph0.x = h0; ph0.y = h1;
            __nv_bfloat162 ph1; ph1.x = h2; ph1.y = h3;
            __nv_bfloat162 pl0 = __floats2bfloat162_rn(
                a0 - __bfloat162float(h0), a1 - __bfloat162float(h1));
            __nv_bfloat162 pl1 = __floats2bfloat162_rn(
                a2 - __bfloat162float(h2), a3 - __bfloat162float(h3));
            uint2 ph, pl;
            ph.x = *reinterpret_cast<unsigned*>(&ph0);
            ph.y = *reinterpret_cast<unsigned*>(&ph1);
            pl.x = *reinterpret_cast<unsigned*>(&pl0);
            pl.y = *reinterpret_cast<unsigned*>(&pl1);
            *(uint2*)((char*)Ah + row * 144 + q * 8) = ph;
            *(uint2*)((char*)Al + row * 144 + q * 8) = pl;
        }
        if (c + 1 < HD / CKA) {
            // prefetch A_{c+1} regs
#pragma unroll
            for (int i = 0; i < 8; ++i) {
                int idx = tid + i * TPBA;
                int row = idx >> 4, q = idx & 15;
                int gr = min(blockIdx.x * TOKA + row, N - 1);
                xr[i] = *(const float4*)(x + (size_t)gr * HD + (c + 1) * CKA + q * 4);
            }
            // prefetch B_{c+1} (both planes) -> other buffer
#pragma unroll
            for (int p = 0; p < 2; ++p) {
                __nv_bfloat16* Bn = B_s + ((1 - b) * 2 + p) * CKA * SBst;
#pragma unroll
                for (int i = 0; i < 2; ++i) {
                    int pp = tid + i * TPBA;
                    int row = pp >> 3, piece = pp & 7;
                    cp_async16((char*)Bn + row * 144 + piece * 16,
                               (const char*)(g_Wbf + p * HD * NE)
                                   + ((size_t)(c + 1) * CKA + row) * 128
                                   + piece * 16);
                }
            }
            CP_COMMIT();
            CP_WAIT1();     // B_c landed, B_{c+1} in flight
        } else {
            CP_WAIT0();
        }
        __syncthreads();    // A_c stored by all threads

#pragma unroll
        for (int kk = 0; kk < 4; ++kk) {
            wmma::fragment<wmma::matrix_a, 16, 16, 16, __nv_bfloat16,
                           wmma::row_major> afh, afl;
            wmma::load_matrix_sync(afh, Ah + (warp * 16) * SA + kk * 16, SA);
            wmma::load_matrix_sync(afl, Al + (warp * 16) * SA + kk * 16, SA);
#pragma unroll
            for (int et = 0; et < 4; ++et) {
                wmma::fragment<wmma::matrix_b, 16, 16, 16, __nv_bfloat16,
                               wmma::row_major> bfh, bfl;
                wmma::load_matrix_sync(bfh, Bh + (kk * 16) * SBst + et * 16, SBst);
                wmma::load_matrix_sync(bfl, Bl + (kk * 16) * SBst + et * 16, SBst);
                wmma::mma_sync(acc[et], afh, bfh, acc[et]);
                wmma::mma_sync(acc[et], afh, bfl, acc[et]);
                wmma::mma_sync(acc[et], afl, bfh, acc[et]);
            }
        }
        __syncthreads();    // MMA_c done before next iteration's STS/cp.async
    }

#pragma unroll
    for (int et = 0; et < 4; ++et)
        wmma::store_matrix_sync(L_s + (warp * 16) * SL + et * 16, acc[et], SL,
                                wmma::mem_row_major);
    if (tid == 0) qn = 0;
    if (tid < NE) h[tid] = 0;
    __syncthreads();

    int amb = 0, slot = 0;
    QEnt ent;
    if (tid < TOKA) {
        float m[8]; int id[8];
#pragma unroll
        for (int s = 0; s < 8; ++s) { m[s] = -1e30f; id[s] = NE; }
#pragma unroll
        for (int q = 0; q < 16; ++q) {
            float4 v = *(const float4*)(L_s + tid * SL + q * 4);
            ins8(v.x, q * 4 + 0, m, id);
            ins8(v.y, q * 4 + 1, m, id);
            ins8(v.z, q * 4 + 2, m, id);
            ins8(v.w, q * 4 + 3, m, id);
        }
        int gt = blockIdx.x * TOKA + tid;
        if (gt < N) {
            if (m[0] - m[1] > T_MARGIN && m[1] - m[2] > T_MARGIN) {
                // near-fp32 logits: ranking provably exact; weights ~2.5e-6 abs
                float tE = expf(m[1] - m[0]);
                float s0 = 1.0f / (1.0f + tE);
                f_idx[2 * gt]     = (float)id[0];
                f_idx[2 * gt + 1] = (float)id[1];
                f_w[2 * gt]       = s0;
                f_w[2 * gt + 1]   = tE * s0;
                atomicAdd(&h[id[0]], 1);
                atomicAdd(&h[id[1]], 1);
            } else {
                amb = 1;
                slot = atomicAdd(&qn, 1);
                ent.tok = gt;
                ent.c0 = (unsigned)id[0] | ((unsigned)id[1] << 8) |
                         ((unsigned)id[2] << 16) | ((unsigned)id[3] << 24);
                ent.c1 = (unsigned)id[4] | ((unsigned)id[5] << 8) |
                         ((unsigned)id[6] << 16) | ((unsigned)id[7] << 24);
                ent.pad = 0;
            }
        }
    }
    __syncthreads();
    if (tid == 0) qb = atomicAdd(&g_qcount, qn);
    __syncthreads();
    if (amb) g_queue[qb + slot] = ent;
    if (tid < NE) g_hist[blockIdx.x * NE + tid] = h[tid];
}

// ---------------------------------------------------------------------------
// K2: exact rescue of queued tokens (unchanged, proven R10). Thread = entry;
// acc[8] exact fp32 sequential-k chains; final idx/w + global hist.
// ---------------------------------------------------------------------------
__global__ void __launch_bounds__(TPBR, 3)
rescue_kernel(const float* __restrict__ x, float* __restrict__ f_idx,
              float* __restrict__ f_w, int N) {
    int qc = g_qcount;
    int base = blockIdx.x * TPBR;
    if (base >= qc) return;
    int n = min(TPBR, qc - base);

    extern __shared__ float smf[];
    float* xs = smf;                        // 2 x 128*WST
    float* ws = smf + 2 * TPBR * WST;       // 2 x 64*WST
    __shared__ int stok[TPBR];

    const int tid = threadIdx.x;
    QEnt q = g_queue[base + min(tid, n - 1)];
    stok[tid] = q.tok;
    int cid[8];
#pragma unroll
    for (int j = 0; j < 4; ++j) cid[j] = (q.c0 >> (8 * j)) & 0xff;
#pragma unroll
    for (int j = 0; j < 4; ++j) cid[4 + j] = (q.c1 >> (8 * j)) & 0xff;
    __syncthreads();

    float acc[8];
#pragma unroll
    for (int j = 0; j < 8; ++j) acc[j] = 0.0f;

#pragma unroll
    for (int i = 0; i < 8; ++i) {
        int idx = tid + i * TPBR;
        int row = idx >> 3, piece = idx & 7;
        cp_async16(xs + row * WST + piece * 4,
                   x + (size_t)stok[row] * HD + piece * 4);
    }
#pragma unroll
    for (int i = 0; i < 4; ++i) {
        int idx = tid + i * TPBR;
        int row = idx >> 3, piece = idx & 7;
        cp_async16(ws + row * WST + piece * 4,
                   g_WT + (size_t)row * HD + piece * 4);
    }
    CP_COMMIT();

    for (int ch = 0; ch < NCHB; ++ch) {
        const int b = ch & 1;
        if (ch + 1 < NCHB) {
            float* xn = xs + (1 - b) * TPBR * WST;
            float* wn = ws + (1 - b) * NE * WST;
#pragma unroll
            for (int i = 0; i < 8; ++i) {
                int idx = tid + i * TPBR;
                int row = idx >> 3, piece = idx & 7;
                cp_async16(xn + row * WST + piece * 4,
                           x + (size_t)stok[row] * HD + (ch + 1) * CKB + piece * 4);
            }
#pragma unroll
            for (int i = 0; i < 4; ++i) {
                int idx = tid + i * TPBR;
                int row = idx >> 3, piece = idx & 7;
                cp_async16(wn + row * WST + piece * 4,
                           g_WT + (size_t)row * HD + (ch + 1) * CKB + piece * 4);
            }
            CP_COMMIT();
            CP_WAIT1();
        } else {
            CP_WAIT0();
        }
        __syncthreads();

        const float* xr = xs + b * TPBR * WST + tid * WST;
        const float* wb = ws + b * NE * WST;
#pragma unroll
        for (int kg = 0; kg < CKB / 4; ++kg) {
            float4 xv = *(const float4*)(xr + kg * 4);
#pragma unroll
            for (int j = 0; j < 8; ++j) {
                float4 wv = *(const float4*)(wb + cid[j] * WST + kg * 4);
                float a = acc[j];
                a = fmaf(xv.x, wv.x, a);
                a = fmaf(xv.y, wv.y, a);
                a = fmaf(xv.z, wv.z, a);
                a = fmaf(xv.w, wv.w, a);
                acc[j] = a;
            }
        }
        __syncthreads();
    }

    if (tid < n) {
        float m0 = -1e30f, m1 = -1e30f;
        int i0 = NE, i1 = NE;
#pragma unroll
        for (int j = 0; j < 8; ++j) {
            float v = acc[j];
            int jd = cid[j];
            if (v > m0 || (v == m0 && jd < i0)) { m1 = m0; i1 = i0; m0 = v; i0 = jd; }
            else if (v > m1 || (v == m1 && jd < i1)) { m1 = v; i1 = jd; }
        }
        int gt = q.tok;
        float tE = expf(m1 - m0);
        float s0 = 1.0f / (1.0f + tE);
        f_idx[2 * gt]     = (float)i0;
        f_idx[2 * gt + 1] = (float)i1;
        f_w[2 * gt]       = s0;
        f_w[2 * gt + 1]   = tE * s0;
        atomicAdd(&g_hist[(gt >> 7) * NE + i0], 1);
        atomicAdd(&g_hist[(gt >> 7) * NE + i1], 1);
    }
}

// ---------------------------------------------------------------------------
// K3: per-expert exclusive scan across 128-token blocks.
// ---------------------------------------------------------------------------
__global__ void scan_kernel(float* __restrict__ out_cnt, int capacity, int NB) {
    int e = blockIdx.x;
    int t = threadIdx.x;    // 256
    __shared__ int ssum[256];
    int P = (NB + 255) >> 8;
    int s = t * P, eidx = min(NB, s + P);
    int sum = 0;
    for (int b = s; b < eidx; ++b) sum += g_hist[b * NE + e];
    ssum[t] = sum;
    __syncthreads();
    for (int off = 1; off < 256; off <<= 1) {
        int u = (t >= off) ? ssum[t - off] : 0;
        __syncthreads();
        ssum[t] += u;
        __syncthreads();
    }
    int run = ssum[t] - sum;
    for (int b = s; b < eidx; ++b) {
        g_base[b * NE + e] = run;
        run += g_hist[b * NE + e];
    }
    if (t == 255) {
        int total = ssum[255];
        out_cnt[e] = (float)min(total, capacity);
        g_edrop[e] = max(0, total - capacity);
    }
}

// ---------------------------------------------------------------------------
// K4: ordered capacity mask + weight normalization (1 warp / 128-token block).
// ---------------------------------------------------------------------------
__global__ void mask_kernel(const float* __restrict__ idxf, float* __restrict__ wf,
                            float* __restrict__ maskf, float* __restrict__ dropf,
                            int capacity, int flat) {
    int b = blockIdx.x;
    int lane = threadIdx.x;
    if (b == 0 && lane == 0) {
        int tot = 0;
        for (int i = 0; i < NE; ++i) tot += g_edrop[i];
        dropf[0] = (float)tot;
    }
    __shared__ int sc[NE];
    for (int e = lane; e < NE; e += 32) sc[e] = g_base[b * NE + e];
    __syncwarp();

    int s = b * (TOKA * TOPK);
    int e_ = min(flat, s + TOKA * TOPK);
    for (int i0 = s; i0 < e_; i0 += 32) {
        int i = i0 + lane;
        bool valid = (i < e_);
        unsigned am = __ballot_sync(0xffffffffu, valid);
        float m = 0.f, w = 0.f;
        if (valid) {
            int ex = (int)idxf[i];
            unsigned grp = __match_any_sync(am, ex);
            int leader = __ffs(grp) - 1;
            int prior = __popc(grp & ((1u << lane) - 1u));
            int base = 0;
            if (lane == leader) {
                base = sc[ex];
                sc[ex] = base + __popc(grp);
            }
            base = __shfl_sync(am, base, leader);
            int pos = base + prior;
            m = (pos < capacity) ? 1.f : 0.f;
            w = wf[i];
        }
        float mo = __shfl_xor_sync(0xffffffffu, m, 1);
        if (valid) {
            float msum = m + mo;
            maskf[i] = m;
            wf[i] = w * m / (msum + 1e-10f);
        }
        __syncwarp();
    }
}

// ---------------------------------------------------------------------------
extern "C" void kernel_launch(void* const* d_in, const int* in_sizes, int n_in,
                              void* d_out, int out_size) {
    const float* x = (const float*)d_in[0];
    const float* W = (const float*)d_in[1];
    if (n_in >= 2 && in_sizes[0] < in_sizes[1]) {
        const float* tmp = x; x = W; W = tmp;
    }
    int N = ((in_sizes[0] >= in_sizes[1]) ? in_sizes[0] : in_sizes[1]) / HD;
    int flat = N * TOPK;
    int NB = (N + TOKA - 1) / TOKA;

    float* out    = (float*)d_out;
    float* f_idx  = out;
    float* f_w    = out + flat;
    float* f_mask = out + 2 * flat;
    float* f_cnt  = out + 3 * flat;
    float* f_drop = f_cnt + NE;

    int capacity = (int)(((double)N * (double)TOPK / (double)NE) * 1.25);

    int smS = (4 * TOKA * SA + 4 * CKA * SBst) * 2;   // 110592
    int smR = (2 * TPBR * WST + 2 * NE * WST) * 4;    // 55296

    cudaFuncSetAttribute(screen_kernel,
                         cudaFuncAttributeMaxDynamicSharedMemorySize, smS);
    cudaFuncSetAttribute(rescue_kernel,
                         cudaFuncAttributeMaxDynamicSharedMemorySize, smR);

    wt_kernel<<<NE, 256>>>(W);
    screen_kernel<<<NB, TPBA, smS>>>(x, f_idx, f_w, N);
    rescue_kernel<<<NB, TPBR, smR>>>(x, f_idx, f_w, N);
    scan_kernel<<<NE, 256>>>(f_cnt, capacity, NB);
    mask_kernel<<<NB, 32>>>(f_idx, f_w, f_mask, f_drop, capacity, flat);
}

// round 14
// speedup vs baseline: 2.7038x; 1.6163x over previous
#include <cuda_runtime.h>
#include <cuda_fp16.h>
#include <mma.h>
#include <cstdint>
#include <math.h>

// ----------------------------------------------------------------------------
// CapacityRouter = 2-pass split-fp16 wmma screen (x->fp16 once, W->fp16 hi+lo;
// logit sigma ~2.8e-4) finalizing high-margin tokens, + exact fp32 rescue of
// ambiguous tokens (top-8 candidates, sequential-k bit-exact chains).
// B-prefetch issued AFTER the per-chunk barrier (fixes R13 buffer race).
// Output: [ idx (N*2) | w (N*2) | mask (N*2) | counters (64) | dropped (1) ]
// ----------------------------------------------------------------------------

#define HD 1024
#define NE 64
#define TOPK 2
#define MAXN (1 << 18)
#define MAXB 8192
#define T_MARGIN 4e-3f

// screen
#define TOKA 128
#define TPBA 256
#define CKA 64
#define SA 72          // A_s stride (half) = 144 B
#define SBst 72        // B_s stride (half) = 144 B
#define SL 68          // logits stride (f32)
#define NCHA (HD / CKA)   // 16

// rescue
#define TPBR 128
#define CKB 32
#define WST 36         // smem row stride (floats) = 144 B
#define NCHB (HD / CKB)   // 32

struct QEnt { int tok; unsigned c0, c1; int pad; };

__device__ QEnt g_queue[MAXN];
__device__ int g_qcount;
__device__ float g_WT[NE * HD];            // fp32 W^T [e][k]  (rescue)
__device__ __half g_Whf[2 * HD * NE];      // plane0 = hi, plane1 = lo (screen)
__device__ int g_hist[MAXB * NE];
__device__ int g_base[MAXB * NE];
__device__ int g_edrop[NE];

using namespace nvcuda;

__device__ __forceinline__ void cp_async16(void* smem_dst, const void* gmem_src) {
    unsigned s = (unsigned)__cvta_generic_to_shared(smem_dst);
    asm volatile("cp.async.ca.shared.global [%0], [%1], 16;\n"
                 :: "r"(s), "l"(gmem_src));
}
#define CP_COMMIT() asm volatile("cp.async.commit_group;\n" ::: "memory")
#define CP_WAIT1()  asm volatile("cp.async.wait_group 1;\n" ::: "memory")
#define CP_WAIT0()  asm volatile("cp.async.wait_group 0;\n" ::: "memory")

// ---------------------------------------------------------------------------
// K0: W^T fp32 (rescue) + fp16 hi/lo planes of W [k][e] (screen B).
// ---------------------------------------------------------------------------
__global__ void wt_kernel(const float* __restrict__ W) {
    int e = blockIdx.x;
    if (e == 0 && threadIdx.x == 0) g_qcount = 0;
    for (int k = threadIdx.x; k < HD; k += blockDim.x) {
        float v = W[k * NE + e];
        g_WT[e * HD + k] = v;
        __half hi = __float2half_rn(v);
        float lo = v - __half2float(hi);
        g_Whf[k * NE + e] = hi;
        g_Whf[HD * NE + k * NE + e] = __float2half_rn(lo);
    }
}

// sorted-8 insertion (descending value, ascending id on ties)
__device__ __forceinline__ void ins8(float v, int j, float* m, int* id) {
    if ((v > m[7]) || (v == m[7] && j < id[7])) {
        m[7] = v; id[7] = j;
#pragma unroll
        for (int s = 7; s > 0; --s) {
            bool b = (m[s] > m[s - 1]) || (m[s] == m[s - 1] && id[s] < id[s - 1]);
            if (b) {
                float tv = m[s]; m[s] = m[s - 1]; m[s - 1] = tv;
                int ti = id[s]; id[s] = id[s - 1]; id[s - 1] = ti;
            }
        }
    }
}

// ---------------------------------------------------------------------------
// K1: 2-pass split-fp16 wmma screen. CTA = 128 tokens x 64 experts.
// acc += A*Bhi + A*Blo (fp32 accum). A double-buffered (STS from regs),
// B triple-buffered (cp.async issued AFTER the barrier -> no overwrite race).
// ONE __syncthreads per chunk.
// ---------------------------------------------------------------------------
__global__ void __launch_bounds__(TPBA, 2)
screen_kernel(const float* __restrict__ x, float* __restrict__ f_idx,
              float* __restrict__ f_w, int N) {
    extern __shared__ char sm[];
    __half* A_s = (__half*)sm;                           // 2 x 128 x SA
    __half* B_s = (__half*)(sm + 2 * TOKA * SA * 2);     // 3 x 2 x 64 x SBst
    float* L_s = (float*)sm;                             // overlay after loop

    __shared__ int h[NE];
    __shared__ int qn, qb;

    const int tid = threadIdx.x;
    const int warp = tid >> 5;

    wmma::fragment<wmma::accumulator, 16, 16, 16, float> acc[4];
#pragma unroll
    for (int et = 0; et < 4; ++et) wmma::fill_fragment(acc[et], 0.0f);

    // prologue: A0 -> regs; B0, B1 (both planes) -> bufs 0,1 (groups G0, G1)
    float4 xr[8];
#pragma unroll
    for (int i = 0; i < 8; ++i) {
        int idx = tid + i * TPBA;
        int row = idx >> 4, q = idx & 15;
        int gr = min(blockIdx.x * TOKA + row, N - 1);
        xr[i] = *(const float4*)(x + (size_t)gr * HD + q * 4);
    }
#pragma unroll
    for (int cc = 0; cc < 2; ++cc) {
#pragma unroll
        for (int p = 0; p < 2; ++p)
#pragma unroll
            for (int i = 0; i < 2; ++i) {
                int pp = tid + i * TPBA;
                int row = pp >> 3, piece = pp & 7;
                cp_async16((char*)(B_s + (cc * 2 + p) * CKA * SBst)
                               + row * 144 + piece * 16,
                           (const char*)(g_Whf + p * HD * NE)
                               + ((size_t)cc * CKA + row) * 128 + piece * 16);
            }
        CP_COMMIT();
    }

    for (int c = 0; c < NCHA; ++c) {
        __half* Ab = A_s + (c & 1) * TOKA * SA;

        // STS A_c (fp32 regs -> fp16). Safe: other buffer than MMA_{c-1}'s A.
#pragma unroll
        for (int i = 0; i < 8; ++i) {
            int idx = tid + i * TPBA;
            int row = idx >> 4, q = idx & 15;
            __half2 p0; p0.x = __float2half_rn(xr[i].x); p0.y = __float2half_rn(xr[i].y);
            __half2 p1; p1.x = __float2half_rn(xr[i].z); p1.y = __float2half_rn(xr[i].w);
            uint2 pk;
            pk.x = *reinterpret_cast<unsigned*>(&p0);
            pk.y = *reinterpret_cast<unsigned*>(&p1);
            *(uint2*)((char*)Ab + row * 144 + q * 8) = pk;
        }
        // prefetch A_{c+1} regs
        if (c + 1 < NCHA) {
#pragma unroll
            for (int i = 0; i < 8; ++i) {
                int idx = tid + i * TPBA;
                int row = idx >> 4, q = idx & 15;
                int gr = min(blockIdx.x * TOKA + row, N - 1);
                xr[i] = *(const float4*)(x + (size_t)gr * HD + (c + 1) * CKA + q * 4);
            }
        }
        CP_WAIT1();               // completes G_c -> B_c resident
        __syncthreads();          // A_c stored by all; MMA_{c-1} done by all

        // NOW safe to overwrite buf (c+2)%3: every warp passed the barrier,
        // so no warp is still reading buf (c-1)%3 == (c+2)%3.
        if (c + 2 < NCHA) {
#pragma unroll
            for (int p = 0; p < 2; ++p)
#pragma unroll
                for (int i = 0; i < 2; ++i) {
                    int pp = tid + i * TPBA;
                    int row = pp >> 3, piece = pp & 7;
                    cp_async16((char*)(B_s + (((c + 2) % 3) * 2 + p) * CKA * SBst)
                                   + row * 144 + piece * 16,
                               (const char*)(g_Whf + p * HD * NE)
                                   + ((size_t)(c + 2) * CKA + row) * 128
                                   + piece * 16);
                }
        }
        CP_COMMIT();              // uniform accounting (G_{c+2}, may be empty)

        __half* Bh = B_s + ((c % 3) * 2 + 0) * CKA * SBst;
        __half* Bl = B_s + ((c % 3) * 2 + 1) * CKA * SBst;
#pragma unroll
        for (int kk = 0; kk < 4; ++kk) {
            wmma::fragment<wmma::matrix_a, 16, 16, 16, __half,
                           wmma::row_major> af;
            wmma::load_matrix_sync(af, Ab + (warp * 16) * SA + kk * 16, SA);
#pragma unroll
            for (int et = 0; et < 4; ++et) {
                wmma::fragment<wmma::matrix_b, 16, 16, 16, __half,
                               wmma::row_major> bf;
                wmma::load_matrix_sync(bf, Bh + (kk * 16) * SBst + et * 16, SBst);
                wmma::mma_sync(acc[et], af, bf, acc[et]);
            }
#pragma unroll
            for (int et = 0; et < 4; ++et) {
                wmma::fragment<wmma::matrix_b, 16, 16, 16, __half,
                               wmma::row_major> bf;
                wmma::load_matrix_sync(bf, Bl + (kk * 16) * SBst + et * 16, SBst);
                wmma::mma_sync(acc[et], af, bf, acc[et]);
            }
        }
    }
    __syncthreads();     // all MMA done before L_s overlay

#pragma unroll
    for (int et = 0; et < 4; ++et)
        wmma::store_matrix_sync(L_s + (warp * 16) * SL + et * 16, acc[et], SL,
                                wmma::mem_row_major);
    if (tid == 0) qn = 0;
    if (tid < NE) h[tid] = 0;
    __syncthreads();

    int amb = 0, slot = 0;
    QEnt ent;
    if (tid < TOKA) {
        float m[8]; int id[8];
#pragma unroll
        for (int s = 0; s < 8; ++s) { m[s] = -1e30f; id[s] = NE; }
#pragma unroll
        for (int q = 0; q < 16; ++q) {
            float4 v = *(const float4*)(L_s + tid * SL + q * 4);
            ins8(v.x, q * 4 + 0, m, id);
            ins8(v.y, q * 4 + 1, m, id);
            ins8(v.z, q * 4 + 2, m, id);
            ins8(v.w, q * 4 + 3, m, id);
        }
        int gt = blockIdx.x * TOKA + tid;
        if (gt < N) {
            if (m[0] - m[1] > T_MARGIN && m[1] - m[2] > T_MARGIN) {
                float tE = expf(m[1] - m[0]);
                float s0 = 1.0f / (1.0f + tE);
                f_idx[2 * gt]     = (float)id[0];
                f_idx[2 * gt + 1] = (float)id[1];
                f_w[2 * gt]       = s0;
                f_w[2 * gt + 1]   = tE * s0;
                atomicAdd(&h[id[0]], 1);
                atomicAdd(&h[id[1]], 1);
            } else {
                amb = 1;
                slot = atomicAdd(&qn, 1);
                ent.tok = gt;
                ent.c0 = (unsigned)id[0] | ((unsigned)id[1] << 8) |
                         ((unsigned)id[2] << 16) | ((unsigned)id[3] << 24);
                ent.c1 = (unsigned)id[4] | ((unsigned)id[5] << 8) |
                         ((unsigned)id[6] << 16) | ((unsigned)id[7] << 24);
                ent.pad = 0;
            }
        }
    }
    __syncthreads();
    if (tid == 0) qb = atomicAdd(&g_qcount, qn);
    __syncthreads();
    if (amb) g_queue[qb + slot] = ent;
    if (tid < NE) g_hist[blockIdx.x * NE + tid] = h[tid];
}

// ---------------------------------------------------------------------------
// K2: exact rescue of queued tokens (proven). Thread = entry; acc[8] exact
// fp32 sequential-k chains; final idx/w + global hist.
// ---------------------------------------------------------------------------
__global__ void __launch_bounds__(TPBR, 3)
rescue_kernel(const float* __restrict__ x, float* __restrict__ f_idx,
              float* __restrict__ f_w, int N) {
    int qc = g_qcount;
    int base = blockIdx.x * TPBR;
    if (base >= qc) return;
    int n = min(TPBR, qc - base);

    extern __shared__ float smf[];
    float* xs = smf;                        // 2 x 128*WST
    float* ws = smf + 2 * TPBR * WST;       // 2 x 64*WST
    __shared__ int stok[TPBR];

    const int tid = threadIdx.x;
    QEnt q = g_queue[base + min(tid, n - 1)];
    stok[tid] = q.tok;
    int cid[8];
#pragma unroll
    for (int j = 0; j < 4; ++j) cid[j] = (q.c0 >> (8 * j)) & 0xff;
#pragma unroll
    for (int j = 0; j < 4; ++j) cid[4 + j] = (q.c1 >> (8 * j)) & 0xff;
    __syncthreads();

    float acc[8];
#pragma unroll
    for (int j = 0; j < 8; ++j) acc[j] = 0.0f;

#pragma unroll
    for (int i = 0; i < 8; ++i) {
        int idx = tid + i * TPBR;
        int row = idx >> 3, piece = idx & 7;
        cp_async16(xs + row * WST + piece * 4,
                   x + (size_t)stok[row] * HD + piece * 4);
    }
#pragma unroll
    for (int i = 0; i < 4; ++i) {
        int idx = tid + i * TPBR;
        int row = idx >> 3, piece = idx & 7;
        cp_async16(ws + row * WST + piece * 4,
                   g_WT + (size_t)row * HD + piece * 4);
    }
    CP_COMMIT();

    for (int ch = 0; ch < NCHB; ++ch) {
        const int b = ch & 1;
        if (ch + 1 < NCHB) {
            float* xn = xs + (1 - b) * TPBR * WST;
            float* wn = ws + (1 - b) * NE * WST;
#pragma unroll
            for (int i = 0; i < 8; ++i) {
                int idx = tid + i * TPBR;
                int row = idx >> 3, piece = idx & 7;
                cp_async16(xn + row * WST + piece * 4,
                           x + (size_t)stok[row] * HD + (ch + 1) * CKB + piece * 4);
            }
#pragma unroll
            for (int i = 0; i < 4; ++i) {
                int idx = tid + i * TPBR;
                int row = idx >> 3, piece = idx & 7;
                cp_async16(wn + row * WST + piece * 4,
                           g_WT + (size_t)row * HD + (ch + 1) * CKB + piece * 4);
            }
            CP_COMMIT();
            CP_WAIT1();
        } else {
            CP_WAIT0();
        }
        __syncthreads();

        const float* xr = xs + b * TPBR * WST + tid * WST;
        const float* wb = ws + b * NE * WST;
#pragma unroll
        for (int kg = 0; kg < CKB / 4; ++kg) {
            float4 xv = *(const float4*)(xr + kg * 4);
#pragma unroll
            for (int j = 0; j < 8; ++j) {
                float4 wv = *(const float4*)(wb + cid[j] * WST + kg * 4);
                float a = acc[j];
                a = fmaf(xv.x, wv.x, a);
                a = fmaf(xv.y, wv.y, a);
                a = fmaf(xv.z, wv.z, a);
                a = fmaf(xv.w, wv.w, a);
                acc[j] = a;
            }
        }
        __syncthreads();
    }

    if (tid < n) {
        float m0 = -1e30f, m1 = -1e30f;
        int i0 = NE, i1 = NE;
#pragma unroll
        for (int j = 0; j < 8; ++j) {
            float v = acc[j];
            int jd = cid[j];
            if (v > m0 || (v == m0 && jd < i0)) { m1 = m0; i1 = i0; m0 = v; i0 = jd; }
            else if (v > m1 || (v == m1 && jd < i1)) { m1 = v; i1 = jd; }
        }
        int gt = q.tok;
        float tE = expf(m1 - m0);
        float s0 = 1.0f / (1.0f + tE);
        f_idx[2 * gt]     = (float)i0;
        f_idx[2 * gt + 1] = (float)i1;
        f_w[2 * gt]       = s0;
        f_w[2 * gt + 1]   = tE * s0;
        atomicAdd(&g_hist[(gt >> 7) * NE + i0], 1);
        atomicAdd(&g_hist[(gt >> 7) * NE + i1], 1);
    }
}

// ---------------------------------------------------------------------------
// K3: per-expert exclusive scan across 128-token blocks.
// ---------------------------------------------------------------------------
__global__ void scan_kernel(float* __restrict__ out_cnt, int capacity, int NB) {
    int e = blockIdx.x;
    int t = threadIdx.x;    // 256
    __shared__ int ssum[256];
    int P = (NB + 255) >> 8;
    int s = t * P, eidx = min(NB, s + P);
    int sum = 0;
    for (int b = s; b < eidx; ++b) sum += g_hist[b * NE + e];
    ssum[t] = sum;
    __syncthreads();
    for (int off = 1; off < 256; off <<= 1) {
        int u = (t >= off) ? ssum[t - off] : 0;
        __syncthreads();
        ssum[t] += u;
        __syncthreads();
    }
    int run = ssum[t] - sum;
    for (int b = s; b < eidx; ++b) {
        g_base[b * NE + e] = run;
        run += g_hist[b * NE + e];
    }
    if (t == 255) {
        int total = ssum[255];
        out_cnt[e] = (float)min(total, capacity);
        g_edrop[e] = max(0, total - capacity);
    }
}

// ---------------------------------------------------------------------------
// K4: ordered capacity mask + weight normalization (1 warp / 128-token block).
// ---------------------------------------------------------------------------
__global__ void mask_kernel(const float* __restrict__ idxf, float* __restrict__ wf,
                            float* __restrict__ maskf, float* __restrict__ dropf,
                            int capacity, int flat) {
    int b = blockIdx.x;
    int lane = threadIdx.x;
    if (b == 0 && lane == 0) {
        int tot = 0;
        for (int i = 0; i < NE; ++i) tot += g_edrop[i];
        dropf[0] = (float)tot;
    }
    __shared__ int sc[NE];
    for (int e = lane; e < NE; e += 32) sc[e] = g_base[b * NE + e];
    __syncwarp();

    int s = b * (TOKA * TOPK);
    int e_ = min(flat, s + TOKA * TOPK);
    for (int i0 = s; i0 < e_; i0 += 32) {
        int i = i0 + lane;
        bool valid = (i < e_);
        unsigned am = __ballot_sync(0xffffffffu, valid);
        float m = 0.f, w = 0.f;
        if (valid) {
            int ex = (int)idxf[i];
            unsigned grp = __match_any_sync(am, ex);
            int leader = __ffs(grp) - 1;
            int prior = __popc(grp & ((1u << lane) - 1u));
            int base = 0;
            if (lane == leader) {
                base = sc[ex];
                sc[ex] = base + __popc(grp);
            }
            base = __shfl_sync(am, base, leader);
            int pos = base + prior;
            m = (pos < capacity) ? 1.f : 0.f;
            w = wf[i];
        }
        float mo = __shfl_xor_sync(0xffffffffu, m, 1);
        if (valid) {
            float msum = m + mo;
            maskf[i] = m;
            wf[i] = w * m / (msum + 1e-10f);
        }
        __syncwarp();
    }
}

// ---------------------------------------------------------------------------
extern "C" void kernel_launch(void* const* d_in, const int* in_sizes, int n_in,
                              void* d_out, int out_size) {
    const float* x = (const float*)d_in[0];
    const float* W = (const float*)d_in[1];
    if (n_in >= 2 && in_sizes[0] < in_sizes[1]) {
        const float* tmp = x; x = W; W = tmp;
    }
    int N = ((in_sizes[0] >= in_sizes[1]) ? in_sizes[0] : in_sizes[1]) / HD;
    int flat = N * TOPK;
    int NB = (N + TOKA - 1) / TOKA;

    float* out    = (float*)d_out;
    float* f_idx  = out;
    float* f_w    = out + flat;
    float* f_mask = out + 2 * flat;
    float* f_cnt  = out + 3 * flat;
    float* f_drop = f_cnt + NE;

    int capacity = (int)(((double)N * (double)TOPK / (double)NE) * 1.25);

    int smS = (2 * TOKA * SA + 6 * CKA * SBst) * 2;   // 92160
    int smR = (2 * TPBR * WST + 2 * NE * WST) * 4;    // 55296

    cudaFuncSetAttribute(screen_kernel,
                         cudaFuncAttributeMaxDynamicSharedMemorySize, smS);
    cudaFuncSetAttribute(rescue_kernel,
                         cudaFuncAttributeMaxDynamicSharedMemorySize, smR);

    wt_kernel<<<NE, 256>>>(W);
    screen_kernel<<<NB, TPBA, smS>>>(x, f_idx, f_w, N);
    rescue_kernel<<<NB, TPBR, smR>>>(x, f_idx, f_w, N);
    scan_kernel<<<NE, 256>>>(f_cnt, capacity, NB);
    mask_kernel<<<NB, 32>>>(f_idx, f_w, f_mask, f_drop, capacity, flat);
}

// round 16
// speedup vs baseline: 2.9798x; 1.1021x over previous
#include <cuda_runtime.h>
#include <cuda_fp16.h>
#include <mma.h>
#include <cstdint>
#include <math.h>

// ----------------------------------------------------------------------------
// CapacityRouter = single-pass fp16 wmma screen (x,W -> fp16; logit sigma
// ~4e-4, calibrated safe) finalizing high-margin tokens, + exact fp32 rescue
// of ambiguous tokens (~4%, top-8 candidates, sequential-k bit-exact chains).
// Output: [ idx (N*2) | w (N*2) | mask (N*2) | counters (64) | dropped (1) ]
// ----------------------------------------------------------------------------

#define HD 1024
#define NE 64
#define TOPK 2
#define MAXN (1 << 18)
#define MAXB 8192
#define T_MARGIN 6e-3f

// screen
#define TOKA 128
#define TPBA 256
#define CKA 64
#define SA 72          // A_s stride (half) = 144 B
#define SBst 72        // B_s stride (half) = 144 B
#define SL 68          // logits stride (f32)
#define NCHA (HD / CKA)   // 16

// rescue
#define TPBR 128
#define CKB 32
#define WST 36         // smem row stride (floats) = 144 B
#define NCHB (HD / CKB)   // 32

struct QEnt { int tok; unsigned c0, c1; int pad; };

__device__ QEnt g_queue[MAXN];
__device__ int g_qcount;
__device__ float g_WT[NE * HD];            // fp32 W^T [e][k]  (rescue)
__device__ __half g_Whf[HD * NE];          // fp16 W [k][e]    (screen B)
__device__ int g_hist[MAXB * NE];
__device__ int g_base[MAXB * NE];
__device__ int g_edrop[NE];

using namespace nvcuda;

__device__ __forceinline__ void cp_async16(void* smem_dst, const void* gmem_src) {
    unsigned s = (unsigned)__cvta_generic_to_shared(smem_dst);
    asm volatile("cp.async.ca.shared.global [%0], [%1], 16;\n"
                 :: "r"(s), "l"(gmem_src));
}
#define CP_COMMIT() asm volatile("cp.async.commit_group;\n" ::: "memory")
#define CP_WAIT1()  asm volatile("cp.async.wait_group 1;\n" ::: "memory")
#define CP_WAIT0()  asm volatile("cp.async.wait_group 0;\n" ::: "memory")

// ---------------------------------------------------------------------------
// K0: W^T fp32 (rescue) + fp16 W [k][e] (screen B).
// ---------------------------------------------------------------------------
__global__ void wt_kernel(const float* __restrict__ W) {
    int e = blockIdx.x;
    if (e == 0 && threadIdx.x == 0) g_qcount = 0;
    for (int k = threadIdx.x; k < HD; k += blockDim.x) {
        float v = W[k * NE + e];
        g_WT[e * HD + k] = v;
        g_Whf[k * NE + e] = __float2half_rn(v);
    }
}

// sorted-8 insertion (descending value, ascending id on ties)
__device__ __forceinline__ void ins8(float v, int j, float* m, int* id) {
    if ((v > m[7]) || (v == m[7] && j < id[7])) {
        m[7] = v; id[7] = j;
#pragma unroll
        for (int s = 7; s > 0; --s) {
            bool b = (m[s] > m[s - 1]) || (m[s] == m[s - 1] && id[s] < id[s - 1]);
            if (b) {
                float tv = m[s]; m[s] = m[s - 1]; m[s - 1] = tv;
                int ti = id[s]; id[s] = id[s - 1]; id[s - 1] = ti;
            }
        }
    }
}

// ---------------------------------------------------------------------------
// K1: single-pass fp16 wmma screen. CTA = 128 tokens x 64 experts.
// A double-buffered (STS from regs), B triple-buffered (cp.async issued
// AFTER the barrier -> no overwrite race). ONE __syncthreads per chunk.
// ---------------------------------------------------------------------------
__global__ void __launch_bounds__(TPBA, 2)
screen_kernel(const float* __restrict__ x, float* __restrict__ f_idx,
              float* __restrict__ f_w, int N) {
    extern __shared__ char sm[];
    __half* A_s = (__half*)sm;                           // 2 x 128 x SA
    __half* B_s = (__half*)(sm + 2 * TOKA * SA * 2);     // 3 x 64 x SBst
    float* L_s = (float*)sm;                             // overlay after loop

    __shared__ int h[NE];
    __shared__ int qn, qb;

    const int tid = threadIdx.x;
    const int warp = tid >> 5;

    wmma::fragment<wmma::accumulator, 16, 16, 16, float> acc[4];
#pragma unroll
    for (int et = 0; et < 4; ++et) wmma::fill_fragment(acc[et], 0.0f);

    // prologue: A0 -> regs; B0, B1 -> bufs 0,1 (groups G0, G1)
    float4 xr[8];
#pragma unroll
    for (int i = 0; i < 8; ++i) {
        int idx = tid + i * TPBA;
        int row = idx >> 4, q = idx & 15;
        int gr = min(blockIdx.x * TOKA + row, N - 1);
        xr[i] = *(const float4*)(x + (size_t)gr * HD + q * 4);
    }
#pragma unroll
    for (int cc = 0; cc < 2; ++cc) {
#pragma unroll
        for (int i = 0; i < 2; ++i) {
            int pp = tid + i * TPBA;
            int row = pp >> 3, piece = pp & 7;
            cp_async16((char*)(B_s + cc * CKA * SBst) + row * 144 + piece * 16,
                       (const char*)g_Whf + ((size_t)cc * CKA + row) * 128
                           + piece * 16);
        }
        CP_COMMIT();
    }

    for (int c = 0; c < NCHA; ++c) {
        __half* Ab = A_s + (c & 1) * TOKA * SA;

        // STS A_c (fp32 regs -> fp16)
#pragma unroll
        for (int i = 0; i < 8; ++i) {
            int idx = tid + i * TPBA;
            int row = idx >> 4, q = idx & 15;
            __half2 p0; p0.x = __float2half_rn(xr[i].x); p0.y = __float2half_rn(xr[i].y);
            __half2 p1; p1.x = __float2half_rn(xr[i].z); p1.y = __float2half_rn(xr[i].w);
            uint2 pk;
            pk.x = *reinterpret_cast<unsigned*>(&p0);
            pk.y = *reinterpret_cast<unsigned*>(&p1);
            *(uint2*)((char*)Ab + row * 144 + q * 8) = pk;
        }
        // prefetch A_{c+1} regs
        if (c + 1 < NCHA) {
#pragma unroll
            for (int i = 0; i < 8; ++i) {
                int idx = tid + i * TPBA;
                int row = idx >> 4, q = idx & 15;
                int gr = min(blockIdx.x * TOKA + row, N - 1);
                xr[i] = *(const float4*)(x + (size_t)gr * HD + (c + 1) * CKA + q * 4);
            }
        }
        CP_WAIT1();               // completes G_c -> B_c resident
        __syncthreads();          // A_c stored by all; MMA_{c-1} done by all

        // safe to overwrite buf (c+2)%3 only after the barrier
        if (c + 2 < NCHA) {
#pragma unroll
            for (int i = 0; i < 2; ++i) {
                int pp = tid + i * TPBA;
                int row = pp >> 3, piece = pp & 7;
                cp_async16((char*)(B_s + ((c + 2) % 3) * CKA * SBst)
                               + row * 144 + piece * 16,
                           (const char*)g_Whf + ((size_t)(c + 2) * CKA + row) * 128
                               + piece * 16);
            }
        }
        CP_COMMIT();              // uniform accounting (G_{c+2}, may be empty)

        __half* Bb = B_s + (c % 3) * CKA * SBst;
#pragma unroll
        for (int kk = 0; kk < 4; ++kk) {
            wmma::fragment<wmma::matrix_a, 16, 16, 16, __half,
                           wmma::row_major> af;
            wmma::load_matrix_sync(af, Ab + (warp * 16) * SA + kk * 16, SA);
#pragma unroll
            for (int et = 0; et < 4; ++et) {
                wmma::fragment<wmma::matrix_b, 16, 16, 16, __half,
                               wmma::row_major> bf;
                wmma::load_matrix_sync(bf, Bb + (kk * 16) * SBst + et * 16, SBst);
                wmma::mma_sync(acc[et], af, bf, acc[et]);
            }
        }
    }
    __syncthreads();     // all MMA done before L_s overlay

#pragma unroll
    for (int et = 0; et < 4; ++et)
        wmma::store_matrix_sync(L_s + (warp * 16) * SL + et * 16, acc[et], SL,
                                wmma::mem_row_major);
    if (tid == 0) qn = 0;
    if (tid < NE) h[tid] = 0;
    __syncthreads();

    int amb = 0, slot = 0;
    QEnt ent;
    if (tid < TOKA) {
        float m[8]; int id[8];
#pragma unroll
        for (int s = 0; s < 8; ++s) { m[s] = -1e30f; id[s] = NE; }
#pragma unroll
        for (int q = 0; q < 16; ++q) {
            float4 v = *(const float4*)(L_s + tid * SL + q * 4);
            ins8(v.x, q * 4 + 0, m, id);
            ins8(v.y, q * 4 + 1, m, id);
            ins8(v.z, q * 4 + 2, m, id);
            ins8(v.w, q * 4 + 3, m, id);
        }
        int gt = blockIdx.x * TOKA + tid;
        if (gt < N) {
            if (m[0] - m[1] > T_MARGIN && m[1] - m[2] > T_MARGIN) {
                float tE = expf(m[1] - m[0]);
                float s0 = 1.0f / (1.0f + tE);
                f_idx[2 * gt]     = (float)id[0];
                f_idx[2 * gt + 1] = (float)id[1];
                f_w[2 * gt]       = s0;
                f_w[2 * gt + 1]   = tE * s0;
                atomicAdd(&h[id[0]], 1);
                atomicAdd(&h[id[1]], 1);
            } else {
                amb = 1;
                slot = atomicAdd(&qn, 1);
                ent.tok = gt;
                ent.c0 = (unsigned)id[0] | ((unsigned)id[1] << 8) |
                         ((unsigned)id[2] << 16) | ((unsigned)id[3] << 24);
                ent.c1 = (unsigned)id[4] | ((unsigned)id[5] << 8) |
                         ((unsigned)id[6] << 16) | ((unsigned)id[7] << 24);
                ent.pad = 0;
            }
        }
    }
    __syncthreads();
    if (tid == 0) qb = atomicAdd(&g_qcount, qn);
    __syncthreads();
    if (amb) g_queue[qb + slot] = ent;
    if (tid < NE) g_hist[blockIdx.x * NE + tid] = h[tid];
}

// ---------------------------------------------------------------------------
// K2: exact rescue of queued tokens (proven). Thread = entry; acc[8] exact
// fp32 sequential-k chains; final idx/w + global hist.
// ---------------------------------------------------------------------------
__global__ void __launch_bounds__(TPBR, 3)
rescue_kernel(const float* __restrict__ x, float* __restrict__ f_idx,
              float* __restrict__ f_w, int N) {
    int qc = g_qcount;
    int base = blockIdx.x * TPBR;
    if (base >= qc) return;
    int n = min(TPBR, qc - base);

    extern __shared__ float smf[];
    float* xs = smf;                        // 2 x 128*WST
    float* ws = smf + 2 * TPBR * WST;       // 2 x 64*WST
    __shared__ int stok[TPBR];

    const int tid = threadIdx.x;
    QEnt q = g_queue[base + min(tid, n - 1)];
    stok[tid] = q.tok;
    int cid[8];
#pragma unroll
    for (int j = 0; j < 4; ++j) cid[j] = (q.c0 >> (8 * j)) & 0xff;
#pragma unroll
    for (int j = 0; j < 4; ++j) cid[4 + j] = (q.c1 >> (8 * j)) & 0xff;
    __syncthreads();

    float acc[8];
#pragma unroll
    for (int j = 0; j < 8; ++j) acc[j] = 0.0f;

#pragma unroll
    for (int i = 0; i < 8; ++i) {
        int idx = tid + i * TPBR;
        int row = idx >> 3, piece = idx & 7;
        cp_async16(xs + row * WST + piece * 4,
                   x + (size_t)stok[row] * HD + piece * 4);
    }
#pragma unroll
    for (int i = 0; i < 4; ++i) {
        int idx = tid + i * TPBR;
        int row = idx >> 3, piece = idx & 7;
        cp_async16(ws + row * WST + piece * 4,
                   g_WT + (size_t)row * HD + piece * 4);
    }
    CP_COMMIT();

    for (int ch = 0; ch < NCHB; ++ch) {
        const int b = ch & 1;
        if (ch + 1 < NCHB) {
            float* xn = xs + (1 - b) * TPBR * WST;
            float* wn = ws + (1 - b) * NE * WST;
#pragma unroll
            for (int i = 0; i < 8; ++i) {
                int idx = tid + i * TPBR;
                int row = idx >> 3, piece = idx & 7;
                cp_async16(xn + row * WST + piece * 4,
                           x + (size_t)stok[row] * HD + (ch + 1) * CKB + piece * 4);
            }
#pragma unroll
            for (int i = 0; i < 4; ++i) {
                int idx = tid + i * TPBR;
                int row = idx >> 3, piece = idx & 7;
                cp_async16(wn + row * WST + piece * 4,
                           g_WT + (size_t)row * HD + (ch + 1) * CKB + piece * 4);
            }
            CP_COMMIT();
            CP_WAIT1();
        } else {
            CP_WAIT0();
        }
        __syncthreads();

        const float* xr = xs + b * TPBR * WST + tid * WST;
        const float* wb = ws + b * NE * WST;
#pragma unroll
        for (int kg = 0; kg < CKB / 4; ++kg) {
            float4 xv = *(const float4*)(xr + kg * 4);
#pragma unroll
            for (int j = 0; j < 8; ++j) {
                float4 wv = *(const float4*)(wb + cid[j] * WST + kg * 4);
                float a = acc[j];
                a = fmaf(xv.x, wv.x, a);
                a = fmaf(xv.y, wv.y, a);
                a = fmaf(xv.z, wv.z, a);
                a = fmaf(xv.w, wv.w, a);
                acc[j] = a;
            }
        }
        __syncthreads();
    }

    if (tid < n) {
        float m0 = -1e30f, m1 = -1e30f;
        int i0 = NE, i1 = NE;
#pragma unroll
        for (int j = 0; j < 8; ++j) {
            float v = acc[j];
            int jd = cid[j];
            if (v > m0 || (v == m0 && jd < i0)) { m1 = m0; i1 = i0; m0 = v; i0 = jd; }
            else if (v > m1 || (v == m1 && jd < i1)) { m1 = v; i1 = jd; }
        }
        int gt = q.tok;
        float tE = expf(m1 - m0);
        float s0 = 1.0f / (1.0f + tE);
        f_idx[2 * gt]     = (float)i0;
        f_idx[2 * gt + 1] = (float)i1;
        f_w[2 * gt]       = s0;
        f_w[2 * gt + 1]   = tE * s0;
        atomicAdd(&g_hist[(gt >> 7) * NE + i0], 1);
        atomicAdd(&g_hist[(gt >> 7) * NE + i1], 1);
    }
}

// ---------------------------------------------------------------------------
// K3: per-expert exclusive scan across 128-token blocks.
// ---------------------------------------------------------------------------
__global__ void scan_kernel(float* __restrict__ out_cnt, int capacity, int NB) {
    int e = blockIdx.x;
    int t = threadIdx.x;    // 256
    __shared__ int ssum[256];
    int P = (NB + 255) >> 8;
    int s = t * P, eidx = min(NB, s + P);
    int sum = 0;
    for (int b = s; b < eidx; ++b) sum += g_hist[b * NE + e];
    ssum[t] = sum;
    __syncthreads();
    for (int off = 1; off < 256; off <<= 1) {
        int u = (t >= off) ? ssum[t - off] : 0;
        __syncthreads();
        ssum[t] += u;
        __syncthreads();
    }
    int run = ssum[t] - sum;
    for (int b = s; b < eidx; ++b) {
        g_base[b * NE + e] = run;
        run += g_hist[b * NE + e];
    }
    if (t == 255) {
        int total = ssum[255];
        out_cnt[e] = (float)min(total, capacity);
        g_edrop[e] = max(0, total - capacity);
    }
}

// ---------------------------------------------------------------------------
// K4: ordered capacity mask + weight normalization (1 warp / 128-token block).
// ---------------------------------------------------------------------------
__global__ void mask_kernel(const float* __restrict__ idxf, float* __restrict__ wf,
                            float* __restrict__ maskf, float* __restrict__ dropf,
                            int capacity, int flat) {
    int b = blockIdx.x;
    int lane = threadIdx.x;
    if (b == 0 && lane == 0) {
        int tot = 0;
        for (int i = 0; i < NE; ++i) tot += g_edrop[i];
        dropf[0] = (float)tot;
    }
    __shared__ int sc[NE];
    for (int e = lane; e < NE; e += 32) sc[e] = g_base[b * NE + e];
    __syncwarp();

    int s = b * (TOKA * TOPK);
    int e_ = min(flat, s + TOKA * TOPK);
    for (int i0 = s; i0 < e_; i0 += 32) {
        int i = i0 + lane;
        bool valid = (i < e_);
        unsigned am = __ballot_sync(0xffffffffu, valid);
        float m = 0.f, w = 0.f;
        if (valid) {
            int ex = (int)idxf[i];
            unsigned grp = __match_any_sync(am, ex);
            int leader = __ffs(grp) - 1;
            int prior = __popc(grp & ((1u << lane) - 1u));
            int base = 0;
            if (lane == leader) {
                base = sc[ex];
                sc[ex] = base + __popc(grp);
            }
            base = __shfl_sync(am, base, leader);
            int pos = base + prior;
            m = (pos < capacity) ? 1.f : 0.f;
            w = wf[i];
        }
        float mo = __shfl_xor_sync(0xffffffffu, m, 1);
        if (valid) {
            float msum = m + mo;
            maskf[i] = m;
            wf[i] = w * m / (msum + 1e-10f);
        }
        __syncwarp();
    }
}

// ---------------------------------------------------------------------------
extern "C" void kernel_launch(void* const* d_in, const int* in_sizes, int n_in,
                              void* d_out, int out_size) {
    const float* x = (const float*)d_in[0];
    const float* W = (const float*)d_in[1];
    if (n_in >= 2 && in_sizes[0] < in_sizes[1]) {
        const float* tmp = x; x = W; W = tmp;
    }
    int N = ((in_sizes[0] >= in_sizes[1]) ? in_sizes[0] : in_sizes[1]) / HD;
    int flat = N * TOPK;
    int NB = (N + TOKA - 1) / TOKA;

    float* out    = (float*)d_out;
    float* f_idx  = out;
    float* f_w    = out + flat;
    float* f_mask = out + 2 * flat;
    float* f_cnt  = out + 3 * flat;
    float* f_drop = f_cnt + NE;

    int capacity = (int)(((double)N * (double)TOPK / (double)NE) * 1.25);

    int smS = (2 * TOKA * SA + 3 * CKA * SBst) * 2;   // 64512
    int smR = (2 * TPBR * WST + 2 * NE * WST) * 4;    // 55296

    cudaFuncSetAttribute(screen_kernel,
                         cudaFuncAttributeMaxDynamicSharedMemorySize, smS);
    cudaFuncSetAttribute(rescue_kernel,
                         cudaFuncAttributeMaxDynamicSharedMemorySize, smR);

    wt_kernel<<<NE, 256>>>(W);
    screen_kernel<<<NB, TPBA, smS>>>(x, f_idx, f_w, N);
    rescue_kernel<<<NB, TPBR, smR>>>(x, f_idx, f_w, N);
    scan_kernel<<<NE, 256>>>(f_cnt, capacity, NB);
    mask_kernel<<<NB, 32>>>(f_idx, f_w, f_mask, f_drop, capacity, flat);
}